// round 14
// baseline (speedup 1.0000x reference)
#include <cuda_runtime.h>
#include <cuda_bf16.h>
#include <cstdint>

// ---------------------------------------------------------------------------
// CrossBundleAttention — R11 + M64 block-tile for skinny GEMMs
// B=64, M=2048, D_LLM=4096, bundles: (d=256,nh=4,s=4) (512,8,8) (1024,16,4)
// ---------------------------------------------------------------------------

#define BATCH 64
#define MEM   2048
#define DLLM  4096
#define STR   72

// ======================= scratch (device globals) ==========================
__device__ float g_prefix[4194304];
__device__ float g_kvf[7340032];
__device__ float g_qb[114688], g_qp[114688], g_o[114688], g_o2[114688];
__device__ float g_u[393216];
__device__ float g_ms[24576];

// ======================= HMMA helpers ======================================
__device__ __forceinline__ void mma16816(float* c, const uint32_t* a, const uint32_t* b) {
    asm volatile(
        "mma.sync.aligned.m16n8k16.row.col.f32.bf16.bf16.f32 "
        "{%0,%1,%2,%3}, {%4,%5,%6,%7}, {%8,%9}, {%0,%1,%2,%3};"
        : "+f"(c[0]), "+f"(c[1]), "+f"(c[2]), "+f"(c[3])
        : "r"(a[0]), "r"(a[1]), "r"(a[2]), "r"(a[3]), "r"(b[0]), "r"(b[1]));
}
__device__ __forceinline__ void ldm4(uint32_t* r, const __nv_bfloat16* p) {
    uint32_t a = (uint32_t)__cvta_generic_to_shared(p);
    asm volatile("ldmatrix.sync.aligned.m8n8.x4.shared.b16 {%0,%1,%2,%3}, [%4];"
        : "=r"(r[0]), "=r"(r[1]), "=r"(r[2]), "=r"(r[3]) : "r"(a));
}
__device__ __forceinline__ uint32_t pack2(__nv_bfloat16 a, __nv_bfloat16 b) {
    __nv_bfloat162 p(a, b);
    return *(uint32_t*)&p;
}
__device__ __forceinline__ void cvt4(float4 v, uint2& hh, uint2& ll) {
    __nv_bfloat16 h0 = __float2bfloat16(v.x), h1 = __float2bfloat16(v.y);
    __nv_bfloat16 h2 = __float2bfloat16(v.z), h3 = __float2bfloat16(v.w);
    __nv_bfloat16 l0 = __float2bfloat16(v.x - __bfloat162float(h0));
    __nv_bfloat16 l1 = __float2bfloat16(v.y - __bfloat162float(h1));
    __nv_bfloat16 l2 = __float2bfloat16(v.z - __bfloat162float(h2));
    __nv_bfloat16 l3 = __float2bfloat16(v.w - __bfloat162float(h3));
    hh.x = pack2(h0, h1); hh.y = pack2(h2, h3);
    ll.x = pack2(l0, l1); ll.y = pack2(l2, l3);
}

#define HMMA_SMEM ((2 * 128 * STR + 2 * 64 * STR) * 2)   // 55296 B (both configs)

// ---------------------------------------------------------------------------
// Fused-conversion hi/lo HMMA GEMM, K-chunk 64.
// M64=false: block tile 128(M) x 64(N), warps 4x2. grid.y = M/128.
// M64=true : block tile  64(M) x 128(N), warps 2x4. grid.y = 1 (M<=64).
// kslice==0: C[z][m][n] = acc + bias[z][n]  (z selects B slice via b_zstr)
// kslice>0 : z = K-slice; atomicAdd(C[m][n], alpha*acc) — C pre-filled w/ bias.
// ---------------------------------------------------------------------------
template<bool M64>
__global__ void __launch_bounds__(256) hmma_f32(
    const float* __restrict__ A, const float* __restrict__ Bm,
    const float* __restrict__ bias, long long bias_zstr,
    float* __restrict__ C, long long c_row, long long c_zstr,
    long long b_zstr, int K, int ldb, int a_rows, int m_valid,
    int kslice, int transB, float alpha)
{
    constexpr int AM = M64 ? 64 : 128;     // A tile rows
    constexpr int BNR = M64 ? 128 : 64;    // B tile rows (output cols per block)
    extern __shared__ __nv_bfloat16 sm[];
    __nv_bfloat16* Ah = sm;
    __nv_bfloat16* Al = sm + AM * STR;
    __nv_bfloat16* Bh = sm + 2 * AM * STR;
    __nv_bfloat16* Bl = Bh + BNR * STR;

    const int tid = threadIdx.x, wid = tid >> 5, lane = tid & 31;
    const int nBase = M64 ? (blockIdx.x << 7) : (blockIdx.x << 6);
    const int mBase = M64 ? 0 : (blockIdx.y << 7);
    const int z = blockIdx.z;

    int k0s, k0e;
    const float* bp;
    if (kslice) {
        k0s = z * kslice; k0e = k0s + kslice;
        bp = Bm;
    } else {
        k0s = 0; k0e = K;
        bp = Bm + (size_t)z * b_zstr;
    }

    const int mW = M64 ? ((wid >> 2) << 5) : ((wid >> 1) << 5);
    const int nW = M64 ? ((wid & 3) << 5) : ((wid & 1) << 5);
    const int grp = lane >> 2, qid = lane & 3;
    const int lane7 = lane & 7, l8 = (lane >> 3) & 1, l16 = (lane >> 4) & 1;
    const int aOff = (lane7 + l8 * 8) * STR + l16 * 8;
    const int bOff = (lane7 + l16 * 8) * STR + l8 * 8;

    const int ar = tid >> 4, ac4 = (tid & 15) << 2;   // 16 rows/pass, 64 cols
    const int kr5 = tid >> 5, nc4 = (tid & 31) << 2;  // transB M64: 8 rows, 128 cols
    float acc[2][4][4] = {};
    float4 pa[AM / 16], pb[M64 ? 8 : 4];

    auto loadA = [&](int k0) {
#pragma unroll
        for (int it = 0; it < AM / 16; it++) {
            const int r = ar + it * 16;
            if (mBase + r < a_rows)
                pa[it] = *(const float4*)(A + (size_t)(mBase + r) * K + k0 + ac4);
            else
                pa[it] = make_float4(0.f, 0.f, 0.f, 0.f);
        }
    };
    auto loadB = [&](int k0) {
        if (!transB) {
#pragma unroll
            for (int it = 0; it < BNR / 16; it++) {
                const int r = ar + it * 16;
                pb[it] = *(const float4*)(bp + (size_t)(nBase + r) * K + k0 + ac4);
            }
        } else if (M64) {
            // B (K, ldb): 64 K-rows x 128 N-cols
#pragma unroll
            for (int it = 0; it < 8; it++) {
                const int kr = kr5 + it * 8;
                pb[it] = *(const float4*)(bp + (size_t)(k0 + kr) * ldb + nBase + nc4);
            }
        } else {
            // B (K, ldb): 64 K-rows x 64 N-cols
#pragma unroll
            for (int it = 0; it < 4; it++) {
                const int kr = ar + it * 16;
                pb[it] = *(const float4*)(bp + (size_t)(k0 + kr) * ldb + nBase + ac4);
            }
        }
    };
    auto storeAB = [&]() {
#pragma unroll
        for (int it = 0; it < AM / 16; it++) {
            const int r = ar + it * 16;
            uint2 hh, ll;
            cvt4(pa[it], hh, ll);
            *(uint2*)(Ah + r * STR + ac4) = hh;
            *(uint2*)(Al + r * STR + ac4) = ll;
        }
        if (!transB) {
#pragma unroll
            for (int it = 0; it < BNR / 16; it++) {
                const int r = ar + it * 16;
                uint2 hh, ll;
                cvt4(pb[it], hh, ll);
                *(uint2*)(Bh + r * STR + ac4) = hh;
                *(uint2*)(Bl + r * STR + ac4) = ll;
            }
        } else if (M64) {
#pragma unroll
            for (int it = 0; it < 8; it++) {
                const int kr = kr5 + it * 8;
                const float vv[4] = {pb[it].x, pb[it].y, pb[it].z, pb[it].w};
#pragma unroll
                for (int j = 0; j < 4; j++) {
                    __nv_bfloat16 h = __float2bfloat16(vv[j]);
                    Bh[(nc4 + j) * STR + kr] = h;
                    Bl[(nc4 + j) * STR + kr] = __float2bfloat16(vv[j] - __bfloat162float(h));
                }
            }
        } else {
#pragma unroll
            for (int it = 0; it < 4; it++) {
                const int kr = ar + it * 16;
                const float vv[4] = {pb[it].x, pb[it].y, pb[it].z, pb[it].w};
#pragma unroll
                for (int j = 0; j < 4; j++) {
                    __nv_bfloat16 h = __float2bfloat16(vv[j]);
                    Bh[(ac4 + j) * STR + kr] = h;
                    Bl[(ac4 + j) * STR + kr] = __float2bfloat16(vv[j] - __bfloat162float(h));
                }
            }
        }
    };

    loadA(k0s);
    loadB(k0s);

    for (int k0 = k0s; k0 < k0e; k0 += 64) {
        __syncthreads();
        storeAB();
        __syncthreads();
        if (k0 + 64 < k0e) {
            loadA(k0 + 64);
            loadB(k0 + 64);
        }

#pragma unroll
        for (int kk = 0; kk < 4; kk++) {
            const int kc = kk << 4;
            uint32_t ah[2][4], al[2][4], bhf[4][2], blf[4][2], t4[4];
#pragma unroll
            for (int mi = 0; mi < 2; mi++) {
                ldm4(ah[mi], Ah + (mW + mi * 16) * STR + kc + aOff);
                ldm4(al[mi], Al + (mW + mi * 16) * STR + kc + aOff);
            }
#pragma unroll
            for (int p = 0; p < 2; p++) {
                ldm4(t4, Bh + (nW + p * 16) * STR + kc + bOff);
                bhf[p * 2][0] = t4[0]; bhf[p * 2][1] = t4[1];
                bhf[p * 2 + 1][0] = t4[2]; bhf[p * 2 + 1][1] = t4[3];
                ldm4(t4, Bl + (nW + p * 16) * STR + kc + bOff);
                blf[p * 2][0] = t4[0]; blf[p * 2][1] = t4[1];
                blf[p * 2 + 1][0] = t4[2]; blf[p * 2 + 1][1] = t4[3];
            }
#pragma unroll
            for (int mi = 0; mi < 2; mi++)
#pragma unroll
                for (int ni = 0; ni < 4; ni++) {
                    mma16816(acc[mi][ni], ah[mi], bhf[ni]);
                    mma16816(acc[mi][ni], ah[mi], blf[ni]);
                    mma16816(acc[mi][ni], al[mi], bhf[ni]);
                }
        }
    }

    if (kslice) {
#pragma unroll
        for (int mi = 0; mi < 2; mi++) {
            const int r0 = mBase + mW + mi * 16 + grp;
#pragma unroll
            for (int ni = 0; ni < 4; ni++) {
                const int c = nBase + nW + ni * 8 + qid * 2;
                if (r0 < m_valid) {
                    atomicAdd(C + (size_t)r0 * c_row + c,     alpha * acc[mi][ni][0]);
                    atomicAdd(C + (size_t)r0 * c_row + c + 1, alpha * acc[mi][ni][1]);
                }
                if (r0 + 8 < m_valid) {
                    atomicAdd(C + (size_t)(r0 + 8) * c_row + c,     alpha * acc[mi][ni][2]);
                    atomicAdd(C + (size_t)(r0 + 8) * c_row + c + 1, alpha * acc[mi][ni][3]);
                }
            }
        }
    } else {
        float* Cz = C + (size_t)z * c_zstr;
        const float* brow = bias + (size_t)z * bias_zstr;
#pragma unroll
        for (int mi = 0; mi < 2; mi++) {
            const int r0 = mBase + mW + mi * 16 + grp;
#pragma unroll
            for (int ni = 0; ni < 4; ni++) {
                const int c = nBase + nW + ni * 8 + qid * 2;
                const float b0 = brow[c], b1 = brow[c + 1];
                if (r0 < m_valid) {
                    float2 v = {acc[mi][ni][0] + b0, acc[mi][ni][1] + b1};
                    *(float2*)(Cz + (size_t)r0 * c_row + c) = v;
                }
                if (r0 + 8 < m_valid) {
                    float2 v = {acc[mi][ni][2] + b0, acc[mi][ni][3] + b1};
                    *(float2*)(Cz + (size_t)(r0 + 8) * c_row + c) = v;
                }
            }
        }
    }
}

// =============== graph root: fill qb/qp/o2 with (scaled) biases =============
__global__ void init_bias(float* __restrict__ qb, float* __restrict__ qp,
                          float* __restrict__ o2,
                          const float* bq0, const float* bq1, const float* bq2,
                          const float* bi0, const float* bi1, const float* bi2,
                          const float* bo0, const float* bo1, const float* bo2)
{
    const int i = blockIdx.x * 256 + threadIdx.x;
    if (i >= 114688) return;
    int n;
    const float *bqv, *biv, *bov;
    if (i < 16384)       { n = i & 255;             bqv = bq0; biv = bi0; bov = bo0; }
    else if (i < 49152)  { n = (i - 16384) & 511;   bqv = bq1; biv = bi1; bov = bo1; }
    else                 { n = (i - 49152) & 1023;  bqv = bq2; biv = bi2; bov = bo2; }
    qb[i] = bqv[n];
    qp[i] = 0.125f * biv[n];
    o2[i] = bov[n];
}

// ======================= split-KV batched attention ========================
__global__ void __launch_bounds__(256) attn_split(
    const float* __restrict__ qp, const float* __restrict__ Kp,
    const float* __restrict__ Vp, const unsigned char* __restrict__ mask,
    float* __restrict__ u, float* __restrict__ ms,
    int d, int mlen, int splits)
{
    extern __shared__ float smf[];
    float* qs = smf;
    float* sc = smf + 512;
    float* ts = smf + 512 + 8 * mlen;

    const int nh = gridDim.x;
    const int h = blockIdx.x, b0 = blockIdx.y << 3, z = blockIdx.z;
    const int base = h << 6;
    const int m0 = z * mlen;
    const int tid = threadIdx.x, lane = tid & 31, wid = tid >> 5;

    for (int i = tid; i < 512; i += 256) {
        int qq = i >> 6, k = i & 63;
        qs[i] = qp[(size_t)(b0 + qq) * d + base + k];
    }
    __syncthreads();

    const float4* qs4 = (const float4*)(qs + (wid << 6));
    const unsigned char* mrow = mask + (size_t)(b0 + wid) * MEM + m0;

    for (int mc = 0; mc < mlen; mc += 64) {
        for (int i = tid; i < 64 * 16; i += 256) {
            int r = i >> 4, c4 = (i & 15) << 2;
            float4 v = *(const float4*)(Kp + (size_t)(m0 + mc + r) * d + base + c4);
            float* dst = ts + r * 65 + c4;
            dst[0] = v.x; dst[1] = v.y; dst[2] = v.z; dst[3] = v.w;
        }
        __syncthreads();
        float acc0 = 0.f, acc1 = 0.f;
        const float* t0 = ts + lane * 65;
        const float* t1 = ts + (lane + 32) * 65;
#pragma unroll
        for (int k4 = 0; k4 < 16; k4++) {
            float4 qv = qs4[k4];
            acc0 += qv.x * t0[k4 * 4] + qv.y * t0[k4 * 4 + 1] + qv.z * t0[k4 * 4 + 2] + qv.w * t0[k4 * 4 + 3];
            acc1 += qv.x * t1[k4 * 4] + qv.y * t1[k4 * 4 + 1] + qv.z * t1[k4 * 4 + 2] + qv.w * t1[k4 * 4 + 3];
        }
        sc[wid * mlen + mc + lane]      = mrow[mc + lane]      ? -1e9f : acc0;
        sc[wid * mlen + mc + 32 + lane] = mrow[mc + 32 + lane] ? -1e9f : acc1;
        __syncthreads();
    }

    float* row = sc + wid * mlen;
    float mx = -1e30f;
    for (int i = lane; i < mlen; i += 32) mx = fmaxf(mx, row[i]);
#pragma unroll
    for (int off = 16; off; off >>= 1) mx = fmaxf(mx, __shfl_xor_sync(0xffffffffu, mx, off));
    float sum = 0.f;
    for (int i = lane; i < mlen; i += 32) {
        float e = __expf(row[i] - mx);
        row[i] = e;
        sum += e;
    }
#pragma unroll
    for (int off = 16; off; off >>= 1) sum += __shfl_xor_sync(0xffffffffu, sum, off);
    if (lane == 0) {
        const int idx = ((b0 + wid) * nh + h) * splits + z;
        ms[idx * 2]     = mx;
        ms[idx * 2 + 1] = sum;
    }

    float acc[8][2] = {};
    for (int mc = 0; mc < mlen; mc += 64) {
        __syncthreads();
        for (int i = tid; i < 64 * 16; i += 256) {
            int r = i >> 4, c4 = (i & 15) << 2;
            float4 v = *(const float4*)(Vp + (size_t)(m0 + mc + r) * d + base + c4);
            float* dst = ts + r * 65 + c4;
            dst[0] = v.x; dst[1] = v.y; dst[2] = v.z; dst[3] = v.w;
        }
        __syncthreads();
        float v0[8], v1[8];
#pragma unroll
        for (int jl = 0; jl < 8; jl++) {
            v0[jl] = ts[(wid * 8 + jl) * 65 + lane];
            v1[jl] = ts[(wid * 8 + jl) * 65 + lane + 32];
        }
        const int jbase = mc + wid * 8;
#pragma unroll
        for (int q = 0; q < 8; q++) {
            float4 pa4 = *(const float4*)(sc + q * mlen + jbase);
            float4 pb4 = *(const float4*)(sc + q * mlen + jbase + 4);
            const float p[8] = {pa4.x, pa4.y, pa4.z, pa4.w, pb4.x, pb4.y, pb4.z, pb4.w};
#pragma unroll
            for (int jl = 0; jl < 8; jl++) {
                acc[q][0] += p[jl] * v0[jl];
                acc[q][1] += p[jl] * v1[jl];
            }
        }
    }

    __syncthreads();
#pragma unroll
    for (int q = 0; q < 8; q++) {
        ts[wid * 512 + q * 64 + lane]      = acc[q][0];
        ts[wid * 512 + q * 64 + lane + 32] = acc[q][1];
    }
    __syncthreads();
    for (int oidx = tid; oidx < 512; oidx += 256) {
        const int q = oidx >> 6, c = oidx & 63;
        float s = 0.f;
#pragma unroll
        for (int w = 0; w < 8; w++) s += ts[w * 512 + oidx];
        u[((size_t)((b0 + q) * nh + h) * splits + z) * 64 + c] = s;
    }
}

__global__ void attn_combine(const float* __restrict__ u, const float* __restrict__ ms,
                             float* __restrict__ o, int d, int nh, int splits)
{
    const int bh = blockIdx.x;
    const int b = bh / nh, h = bh % nh, c = threadIdx.x;
    float M = -1e30f;
    for (int z = 0; z < splits; z++) M = fmaxf(M, ms[(bh * splits + z) * 2]);
    float S = 0.f, O = 0.f;
    for (int z = 0; z < splits; z++) {
        const float w = __expf(ms[(bh * splits + z) * 2] - M);
        S += w * ms[(bh * splits + z) * 2 + 1];
        O += w * u[((size_t)bh * splits + z) * 64 + c];
    }
    o[(size_t)b * d + (h << 6) + c] = O / S;
}

// ======================= per-bundle LayerNorm ==============================
__global__ void __launch_bounds__(256) ln_kernel(
    const float* __restrict__ x, const float* __restrict__ g,
    const float* __restrict__ be, float* __restrict__ out,
    int slotBase, int nslots)
{
    __shared__ float rs[8], rss[8];
    __shared__ float s_mu, s_inv;
    const int bi = blockIdx.x / nslots, slot = slotBase + blockIdx.x % nslots;
    const int rowi = bi * 16 + slot;
    const float4* xr = (const float4*)(x + (size_t)rowi * DLLM);
    const int tid = threadIdx.x, lane = tid & 31, warp = tid >> 5;
    float s = 0.f, ss = 0.f;
    for (int i = tid; i < DLLM / 4; i += 256) {
        float4 v = xr[i];
        s  += v.x + v.y + v.z + v.w;
        ss += v.x * v.x + v.y * v.y + v.z * v.z + v.w * v.w;
    }
#pragma unroll
    for (int off = 16; off; off >>= 1) {
        s  += __shfl_xor_sync(0xffffffffu, s, off);
        ss += __shfl_xor_sync(0xffffffffu, ss, off);
    }
    if (lane == 0) { rs[warp] = s; rss[warp] = ss; }
    __syncthreads();
    if (tid == 0) {
        float S = 0.f, SS = 0.f;
#pragma unroll
        for (int w = 0; w < 8; w++) { S += rs[w]; SS += rss[w]; }
        const float mu = S * (1.0f / DLLM);
        const float var = SS * (1.0f / DLLM) - mu * mu;
        s_mu = mu;
        s_inv = rsqrtf(var + 1e-5f);
    }
    __syncthreads();
    const float mu = s_mu, inv = s_inv;
    const float4* g4 = (const float4*)g;
    const float4* b4 = (const float4*)be;
    float4* outr = (float4*)(out + (size_t)rowi * DLLM);
    for (int i = tid; i < DLLM / 4; i += 256) {
        float4 v = xr[i], gv = g4[i], bv = b4[i];
        float4 r;
        r.x = (v.x - mu) * inv * gv.x + bv.x;
        r.y = (v.y - mu) * inv * gv.y + bv.y;
        r.z = (v.z - mu) * inv * gv.z + bv.z;
        r.w = (v.w - mu) * inv * gv.w + bv.w;
        outr[i] = r;
    }
}

// ======================= streams/events ====================================
struct StreamInit {
    cudaStream_t sA[3], sB[3];
    cudaEvent_t evFork, evKV[3], evD[3];
    StreamInit() {
        for (int i = 0; i < 3; i++) {
            cudaStreamCreateWithFlags(&sA[i], cudaStreamNonBlocking);
            cudaStreamCreateWithFlags(&sB[i], cudaStreamNonBlocking);
            cudaEventCreateWithFlags(&evKV[i], cudaEventDisableTiming);
            cudaEventCreateWithFlags(&evD[i], cudaEventDisableTiming);
        }
        cudaEventCreateWithFlags(&evFork, cudaEventDisableTiming);
    }
};
static StreamInit g_si;

// ======================= host orchestration ================================
extern "C" void kernel_launch(void* const* d_in, const int* in_sizes, int n_in,
                              void* d_out, int out_size)
{
    const float* hidden = (const float*)d_in[0];
    const float* fibers[3] = {(const float*)d_in[1], (const float*)d_in[2], (const float*)d_in[3]};
    const unsigned char* mask = (const unsigned char*)d_in[4];
    const float* Wq[3]    = {(const float*)d_in[5],  (const float*)d_in[7],  (const float*)d_in[9]};
    const float* bq[3]    = {(const float*)d_in[6],  (const float*)d_in[8],  (const float*)d_in[10]};
    const float* Wqkv[3]  = {(const float*)d_in[11], (const float*)d_in[15], (const float*)d_in[19]};
    const float* bqkv[3]  = {(const float*)d_in[12], (const float*)d_in[16], (const float*)d_in[20]};
    const float* Wo[3]    = {(const float*)d_in[13], (const float*)d_in[17], (const float*)d_in[21]};
    const float* bo[3]    = {(const float*)d_in[14], (const float*)d_in[18], (const float*)d_in[22]};
    const float* Wlift[3] = {(const float*)d_in[23], (const float*)d_in[25], (const float*)d_in[27]};
    const float* blift[3] = {(const float*)d_in[24], (const float*)d_in[26], (const float*)d_in[28]};
    const float* lng = (const float*)d_in[29];
    const float* lnb = (const float*)d_in[30];

    const int ds[3]       = {256, 512, 1024};
    const int nhs[3]      = {4, 8, 16};
    const int slots[3]    = {4, 8, 4};
    const int slotBase[3] = {0, 4, 12};
    const int splits[3]   = {8, 4, 2};
    const size_t kvfOff[3]= {0, 1048576, 3145728};
    const size_t bOff[3]  = {0, 16384, 49152};
    const size_t uOff[3]  = {0, 131072, 262144};
    const size_t msOff[3] = {0, 4096, 8192};

    float *prefix, *kvf, *qb, *qp, *oo, *o2, *uu, *msb;
    cudaGetSymbolAddress((void**)&prefix, g_prefix);
    cudaGetSymbolAddress((void**)&kvf, g_kvf);
    cudaGetSymbolAddress((void**)&qb, g_qb);
    cudaGetSymbolAddress((void**)&qp, g_qp);
    cudaGetSymbolAddress((void**)&oo, g_o);
    cudaGetSymbolAddress((void**)&o2, g_o2);
    cudaGetSymbolAddress((void**)&uu, g_u);
    cudaGetSymbolAddress((void**)&msb, g_ms);

    cudaFuncSetAttribute(hmma_f32<false>, cudaFuncAttributeMaxDynamicSharedMemorySize, HMMA_SMEM);
    cudaFuncSetAttribute(hmma_f32<true>,  cudaFuncAttributeMaxDynamicSharedMemorySize, HMMA_SMEM);
    cudaFuncSetAttribute(attn_split, cudaFuncAttributeMaxDynamicSharedMemorySize,
                         (512 + 8 * 1024 + 4160) * 4);

    init_bias<<<(114688 + 255) / 256, 256>>>(qb, qp, o2,
        bq[0], bq[1], bq[2], bqkv[0], bqkv[1], bqkv[2], bo[0], bo[1], bo[2]);
    cudaEventRecord(g_si.evFork, 0);

    for (int b = 0; b < 3; b++) {
        const int d = ds[b], nh = nhs[b], s = slots[b], sp = splits[b];
        const int mlen = MEM / sp;
        const int attn_smem = (512 + 8 * mlen + 4160) * 4;
        cudaStream_t A = g_si.sA[b], Bs = g_si.sB[b];

        // ---- stream A: KV projection (M128 tile) ----
        cudaStreamWaitEvent(A, g_si.evFork, 0);
        hmma_f32<false><<<dim3(d / 64, MEM / 128, 2), 256, HMMA_SMEM, A>>>(
            fibers[b], Wqkv[b] + (size_t)d * d, bqkv[b] + d, d,
            kvf + kvfOff[b], d, (long long)MEM * d,
            (long long)d * d, d, d, MEM, MEM, 0, 0, 1.0f);
        cudaEventRecord(g_si.evKV[b], A);

        // ---- stream B: q chain -> attention -> out-proj -> lift -> LN ----
        cudaStreamWaitEvent(Bs, g_si.evFork, 0);
        // q-head: M64 tile, K=4096 split 16x256, atomic
        hmma_f32<true><<<dim3(d / 128, 1, 16), 256, HMMA_SMEM, Bs>>>(
            hidden, Wq[b], nullptr, 0,
            qb + bOff[b], d, 0,
            0, DLLM, DLLM, BATCH, BATCH, 256, 0, 1.0f);
        // q in-proj: M64, K split 4, alpha 0.125
        hmma_f32<true><<<dim3(d / 128, 1, 4), 256, HMMA_SMEM, Bs>>>(
            qb + bOff[b], Wqkv[b], nullptr, 0,
            qp + bOff[b], d, 0,
            0, d, d, BATCH, BATCH, d / 4, 0, 0.125f);
        cudaStreamWaitEvent(Bs, g_si.evKV[b], 0);
        attn_split<<<dim3(nh, BATCH / 8, sp), 256, attn_smem, Bs>>>(
            qp + bOff[b], kvf + kvfOff[b], kvf + kvfOff[b] + (size_t)MEM * d, mask,
            uu + uOff[b], msb + msOff[b], d, mlen, sp);
        attn_combine<<<BATCH * nh, 64, 0, Bs>>>(
            uu + uOff[b], msb + msOff[b], oo + bOff[b], d, nh, sp);
        // out-proj: M64, K split 4
        hmma_f32<true><<<dim3(d / 128, 1, 4), 256, HMMA_SMEM, Bs>>>(
            oo + bOff[b], Wo[b], nullptr, 0,
            o2 + bOff[b], d, 0,
            0, d, d, BATCH, BATCH, d / 4, 0, 1.0f);
        // lift: M64, transB, z = slot
        hmma_f32<true><<<dim3(DLLM / 128, 1, s), 256, HMMA_SMEM, Bs>>>(
            o2 + bOff[b], Wlift[b], blift[b], DLLM,
            prefix + (size_t)slotBase[b] * DLLM, 16 * DLLM, DLLM,
            (long long)d * DLLM, d, DLLM, BATCH, BATCH, 0, 1, 1.0f);
        ln_kernel<<<BATCH * s, 256, 0, Bs>>>(
            prefix, lng, lnb, (float*)d_out, slotBase[b], s);
        cudaEventRecord(g_si.evD[b], Bs);
    }

    for (int b = 0; b < 3; b++) cudaStreamWaitEvent(0, g_si.evD[b], 0);
}

// round 15
// speedup vs baseline: 1.3377x; 1.3377x over previous
#include <cuda_runtime.h>
#include <cuda_bf16.h>
#include <cuda_fp16.h>
#include <cstdint>

// ---------------------------------------------------------------------------
// CrossBundleAttention — R11 + fp16 single-pass KV-proj + 100% smem carveout
// B=64, M=2048, D_LLM=4096, bundles: (d=256,nh=4,s=4) (512,8,8) (1024,16,4)
// ---------------------------------------------------------------------------

#define BATCH 64
#define MEM   2048
#define DLLM  4096
#define STR   72

// ======================= scratch (device globals) ==========================
__device__ float g_prefix[4194304];
__device__ float g_kvf[7340032];
__device__ float g_qb[114688], g_qp[114688], g_o[114688], g_o2[114688];
__device__ float g_u[393216];
__device__ float g_ms[24576];

// ======================= MMA helpers =======================================
__device__ __forceinline__ void mma16816(float* c, const uint32_t* a, const uint32_t* b) {
    asm volatile(
        "mma.sync.aligned.m16n8k16.row.col.f32.bf16.bf16.f32 "
        "{%0,%1,%2,%3}, {%4,%5,%6,%7}, {%8,%9}, {%0,%1,%2,%3};"
        : "+f"(c[0]), "+f"(c[1]), "+f"(c[2]), "+f"(c[3])
        : "r"(a[0]), "r"(a[1]), "r"(a[2]), "r"(a[3]), "r"(b[0]), "r"(b[1]));
}
__device__ __forceinline__ void mma16816h(float* c, const uint32_t* a, const uint32_t* b) {
    asm volatile(
        "mma.sync.aligned.m16n8k16.row.col.f32.f16.f16.f32 "
        "{%0,%1,%2,%3}, {%4,%5,%6,%7}, {%8,%9}, {%0,%1,%2,%3};"
        : "+f"(c[0]), "+f"(c[1]), "+f"(c[2]), "+f"(c[3])
        : "r"(a[0]), "r"(a[1]), "r"(a[2]), "r"(a[3]), "r"(b[0]), "r"(b[1]));
}
__device__ __forceinline__ void ldm4(uint32_t* r, const void* p) {
    uint32_t a = (uint32_t)__cvta_generic_to_shared(p);
    asm volatile("ldmatrix.sync.aligned.m8n8.x4.shared.b16 {%0,%1,%2,%3}, [%4];"
        : "=r"(r[0]), "=r"(r[1]), "=r"(r[2]), "=r"(r[3]) : "r"(a));
}
__device__ __forceinline__ uint32_t pack2(__nv_bfloat16 a, __nv_bfloat16 b) {
    __nv_bfloat162 p(a, b);
    return *(uint32_t*)&p;
}
__device__ __forceinline__ void cvt4(float4 v, uint2& hh, uint2& ll) {
    __nv_bfloat16 h0 = __float2bfloat16(v.x), h1 = __float2bfloat16(v.y);
    __nv_bfloat16 h2 = __float2bfloat16(v.z), h3 = __float2bfloat16(v.w);
    __nv_bfloat16 l0 = __float2bfloat16(v.x - __bfloat162float(h0));
    __nv_bfloat16 l1 = __float2bfloat16(v.y - __bfloat162float(h1));
    __nv_bfloat16 l2 = __float2bfloat16(v.z - __bfloat162float(h2));
    __nv_bfloat16 l3 = __float2bfloat16(v.w - __bfloat162float(h3));
    hh.x = pack2(h0, h1); hh.y = pack2(h2, h3);
    ll.x = pack2(l0, l1); ll.y = pack2(l2, l3);
}
__device__ __forceinline__ uint2 cvt4h(float4 v) {
    __half2 p0 = __floats2half2_rn(v.x, v.y);
    __half2 p1 = __floats2half2_rn(v.z, v.w);
    uint2 r;
    r.x = *(uint32_t*)&p0;
    r.y = *(uint32_t*)&p1;
    return r;
}

#define HMMA_SMEM ((2 * 128 * STR + 2 * 64 * STR) * 2)   // 55296 B
#define KV16_SMEM ((128 * STR + 64 * STR) * 2)           // 27648 B

// ---------------------------------------------------------------------------
// bf16 hi/lo HMMA GEMM (R11, unchanged).
// ---------------------------------------------------------------------------
__global__ void __launch_bounds__(256) hmma_f32(
    const float* __restrict__ A, const float* __restrict__ Bm,
    const float* __restrict__ bias, long long bias_zstr,
    float* __restrict__ C, long long c_row, long long c_zstr,
    long long b_zstr, int K, int ldb, int a_rows, int m_valid,
    int kslice, int transB, float alpha)
{
    extern __shared__ __nv_bfloat16 sm[];
    __nv_bfloat16* Ah = sm;
    __nv_bfloat16* Al = sm + 128 * STR;
    __nv_bfloat16* Bh = sm + 2 * 128 * STR;
    __nv_bfloat16* Bl = Bh + 64 * STR;

    const int tid = threadIdx.x, wid = tid >> 5, lane = tid & 31;
    const int nBase = blockIdx.x << 6, mBase = blockIdx.y << 7, z = blockIdx.z;

    int k0s, k0e;
    const float* bp;
    if (kslice) {
        k0s = z * kslice; k0e = k0s + kslice;
        bp = Bm;
    } else {
        k0s = 0; k0e = K;
        bp = Bm + (size_t)z * b_zstr;
    }

    const int mW = (wid >> 1) << 5;
    const int nW = (wid & 1) << 5;
    const int grp = lane >> 2, qid = lane & 3;
    const int lane7 = lane & 7, l8 = (lane >> 3) & 1, l16 = (lane >> 4) & 1;
    const int aOff = (lane7 + l8 * 8) * STR + l16 * 8;
    const int bOff = (lane7 + l16 * 8) * STR + l8 * 8;

    const int ar = tid >> 4, ac4 = (tid & 15) << 2;
    float acc[2][4][4] = {};
    float4 pa[8], pb[4];

    auto loadA = [&](int k0) {
#pragma unroll
        for (int it = 0; it < 8; it++) {
            const int r = ar + it * 16;
            if (mBase + r < a_rows)
                pa[it] = *(const float4*)(A + (size_t)(mBase + r) * K + k0 + ac4);
            else
                pa[it] = make_float4(0.f, 0.f, 0.f, 0.f);
        }
    };
    auto loadB = [&](int k0) {
        if (!transB) {
#pragma unroll
            for (int it = 0; it < 4; it++) {
                const int r = ar + it * 16;
                pb[it] = *(const float4*)(bp + (size_t)(nBase + r) * K + k0 + ac4);
            }
        } else {
#pragma unroll
            for (int it = 0; it < 4; it++) {
                const int kr = ar + it * 16;
                pb[it] = *(const float4*)(bp + (size_t)(k0 + kr) * ldb + nBase + ac4);
            }
        }
    };
    auto storeAB = [&]() {
#pragma unroll
        for (int it = 0; it < 8; it++) {
            const int r = ar + it * 16;
            uint2 hh, ll;
            cvt4(pa[it], hh, ll);
            *(uint2*)(Ah + r * STR + ac4) = hh;
            *(uint2*)(Al + r * STR + ac4) = ll;
        }
        if (!transB) {
#pragma unroll
            for (int it = 0; it < 4; it++) {
                const int r = ar + it * 16;
                uint2 hh, ll;
                cvt4(pb[it], hh, ll);
                *(uint2*)(Bh + r * STR + ac4) = hh;
                *(uint2*)(Bl + r * STR + ac4) = ll;
            }
        } else {
#pragma unroll
            for (int it = 0; it < 4; it++) {
                const int kr = ar + it * 16;
                const float vv[4] = {pb[it].x, pb[it].y, pb[it].z, pb[it].w};
#pragma unroll
                for (int j = 0; j < 4; j++) {
                    __nv_bfloat16 h = __float2bfloat16(vv[j]);
                    Bh[(ac4 + j) * STR + kr] = h;
                    Bl[(ac4 + j) * STR + kr] = __float2bfloat16(vv[j] - __bfloat162float(h));
                }
            }
        }
    };

    loadA(k0s);
    loadB(k0s);

    for (int k0 = k0s; k0 < k0e; k0 += 64) {
        __syncthreads();
        storeAB();
        __syncthreads();
        if (k0 + 64 < k0e) {
            loadA(k0 + 64);
            loadB(k0 + 64);
        }

#pragma unroll
        for (int kk = 0; kk < 4; kk++) {
            const int kc = kk << 4;
            uint32_t ah[2][4], al[2][4], bhf[4][2], blf[4][2], t4[4];
#pragma unroll
            for (int mi = 0; mi < 2; mi++) {
                ldm4(ah[mi], Ah + (mW + mi * 16) * STR + kc + aOff);
                ldm4(al[mi], Al + (mW + mi * 16) * STR + kc + aOff);
            }
#pragma unroll
            for (int p = 0; p < 2; p++) {
                ldm4(t4, Bh + (nW + p * 16) * STR + kc + bOff);
                bhf[p * 2][0] = t4[0]; bhf[p * 2][1] = t4[1];
                bhf[p * 2 + 1][0] = t4[2]; bhf[p * 2 + 1][1] = t4[3];
                ldm4(t4, Bl + (nW + p * 16) * STR + kc + bOff);
                blf[p * 2][0] = t4[0]; blf[p * 2][1] = t4[1];
                blf[p * 2 + 1][0] = t4[2]; blf[p * 2 + 1][1] = t4[3];
            }
#pragma unroll
            for (int mi = 0; mi < 2; mi++)
#pragma unroll
                for (int ni = 0; ni < 4; ni++) {
                    mma16816(acc[mi][ni], ah[mi], bhf[ni]);
                    mma16816(acc[mi][ni], ah[mi], blf[ni]);
                    mma16816(acc[mi][ni], al[mi], bhf[ni]);
                }
        }
    }

    if (kslice) {
#pragma unroll
        for (int mi = 0; mi < 2; mi++) {
            const int r0 = mBase + mW + mi * 16 + grp;
#pragma unroll
            for (int ni = 0; ni < 4; ni++) {
                const int c = nBase + nW + ni * 8 + qid * 2;
                if (r0 < m_valid) {
                    atomicAdd(C + (size_t)r0 * c_row + c,     alpha * acc[mi][ni][0]);
                    atomicAdd(C + (size_t)r0 * c_row + c + 1, alpha * acc[mi][ni][1]);
                }
                if (r0 + 8 < m_valid) {
                    atomicAdd(C + (size_t)(r0 + 8) * c_row + c,     alpha * acc[mi][ni][2]);
                    atomicAdd(C + (size_t)(r0 + 8) * c_row + c + 1, alpha * acc[mi][ni][3]);
                }
            }
        }
    } else {
        float* Cz = C + (size_t)z * c_zstr;
        const float* brow = bias + (size_t)z * bias_zstr;
#pragma unroll
        for (int mi = 0; mi < 2; mi++) {
            const int r0 = mBase + mW + mi * 16 + grp;
#pragma unroll
            for (int ni = 0; ni < 4; ni++) {
                const int c = nBase + nW + ni * 8 + qid * 2;
                const float b0 = brow[c], b1 = brow[c + 1];
                if (r0 < m_valid) {
                    float2 v = {acc[mi][ni][0] + b0, acc[mi][ni][1] + b1};
                    *(float2*)(Cz + (size_t)r0 * c_row + c) = v;
                }
                if (r0 + 8 < m_valid) {
                    float2 v = {acc[mi][ni][2] + b0, acc[mi][ni][3] + b1};
                    *(float2*)(Cz + (size_t)(r0 + 8) * c_row + c) = v;
                }
            }
        }
    }
}

// ---------------------------------------------------------------------------
// fp16 single-pass GEMM-NT for KV projection.
// C[z][m][n] = A[m][:]·B_z[n][:] + bias[z][n];  z in {0,1} selects Wk/Wv.
// Block tile 128x64, 8 warps (4x2), K-chunk 64. smem 27.6 KB.
// ---------------------------------------------------------------------------
__global__ void __launch_bounds__(256) hmma_kv16(
    const float* __restrict__ A, const float* __restrict__ Bm,
    const float* __restrict__ bias, long long bias_zstr,
    float* __restrict__ C, long long c_row, long long c_zstr,
    long long b_zstr, int K)
{
    extern __shared__ __half smh[];
    __half* Ah = smh;
    __half* Bh = smh + 128 * STR;

    const int tid = threadIdx.x, wid = tid >> 5, lane = tid & 31;
    const int nBase = blockIdx.x << 6, mBase = blockIdx.y << 7, z = blockIdx.z;
    const float* bp = Bm + (size_t)z * b_zstr;

    const int mW = (wid >> 1) << 5;
    const int nW = (wid & 1) << 5;
    const int grp = lane >> 2, qid = lane & 3;
    const int lane7 = lane & 7, l8 = (lane >> 3) & 1, l16 = (lane >> 4) & 1;
    const int aOff = (lane7 + l8 * 8) * STR + l16 * 8;
    const int bOff = (lane7 + l16 * 8) * STR + l8 * 8;

    const int ar = tid >> 4, ac4 = (tid & 15) << 2;
    float acc[2][4][4] = {};
    float4 pa[8], pb[4];

    auto loadA = [&](int k0) {
#pragma unroll
        for (int it = 0; it < 8; it++) {
            const int r = ar + it * 16;
            pa[it] = *(const float4*)(A + (size_t)(mBase + r) * K + k0 + ac4);
        }
    };
    auto loadB = [&](int k0) {
#pragma unroll
        for (int it = 0; it < 4; it++) {
            const int r = ar + it * 16;
            pb[it] = *(const float4*)(bp + (size_t)(nBase + r) * K + k0 + ac4);
        }
    };
    auto storeAB = [&]() {
#pragma unroll
        for (int it = 0; it < 8; it++)
            *(uint2*)(Ah + (ar + it * 16) * STR + ac4) = cvt4h(pa[it]);
#pragma unroll
        for (int it = 0; it < 4; it++)
            *(uint2*)(Bh + (ar + it * 16) * STR + ac4) = cvt4h(pb[it]);
    };

    loadA(0);
    loadB(0);

    for (int k0 = 0; k0 < K; k0 += 64) {
        __syncthreads();
        storeAB();
        __syncthreads();
        if (k0 + 64 < K) {
            loadA(k0 + 64);
            loadB(k0 + 64);
        }

#pragma unroll
        for (int kk = 0; kk < 4; kk++) {
            const int kc = kk << 4;
            uint32_t ah[2][4], bhf[4][2], t4[4];
#pragma unroll
            for (int mi = 0; mi < 2; mi++)
                ldm4(ah[mi], Ah + (mW + mi * 16) * STR + kc + aOff);
#pragma unroll
            for (int p = 0; p < 2; p++) {
                ldm4(t4, Bh + (nW + p * 16) * STR + kc + bOff);
                bhf[p * 2][0] = t4[0]; bhf[p * 2][1] = t4[1];
                bhf[p * 2 + 1][0] = t4[2]; bhf[p * 2 + 1][1] = t4[3];
            }
#pragma unroll
            for (int mi = 0; mi < 2; mi++)
#pragma unroll
                for (int ni = 0; ni < 4; ni++)
                    mma16816h(acc[mi][ni], ah[mi], bhf[ni]);
        }
    }

    float* Cz = C + (size_t)z * c_zstr;
    const float* brow = bias + (size_t)z * bias_zstr;
#pragma unroll
    for (int mi = 0; mi < 2; mi++) {
        const int r0 = mBase + mW + mi * 16 + grp;
#pragma unroll
        for (int ni = 0; ni < 4; ni++) {
            const int c = nBase + nW + ni * 8 + qid * 2;
            const float b0 = brow[c], b1 = brow[c + 1];
            float2 v0 = {acc[mi][ni][0] + b0, acc[mi][ni][1] + b1};
            *(float2*)(Cz + (size_t)r0 * c_row + c) = v0;
            float2 v1 = {acc[mi][ni][2] + b0, acc[mi][ni][3] + b1};
            *(float2*)(Cz + (size_t)(r0 + 8) * c_row + c) = v1;
        }
    }
}

// =============== graph root: fill qb/qp/o2 with (scaled) biases =============
__global__ void init_bias(float* __restrict__ qb, float* __restrict__ qp,
                          float* __restrict__ o2,
                          const float* bq0, const float* bq1, const float* bq2,
                          const float* bi0, const float* bi1, const float* bi2,
                          const float* bo0, const float* bo1, const float* bo2)
{
    const int i = blockIdx.x * 256 + threadIdx.x;
    if (i >= 114688) return;
    int n;
    const float *bqv, *biv, *bov;
    if (i < 16384)       { n = i & 255;             bqv = bq0; biv = bi0; bov = bo0; }
    else if (i < 49152)  { n = (i - 16384) & 511;   bqv = bq1; biv = bi1; bov = bo1; }
    else                 { n = (i - 49152) & 1023;  bqv = bq2; biv = bi2; bov = bo2; }
    qb[i] = bqv[n];
    qp[i] = 0.125f * biv[n];
    o2[i] = bov[n];
}

// ======================= split-KV batched attention ========================
__global__ void __launch_bounds__(256) attn_split(
    const float* __restrict__ qp, const float* __restrict__ Kp,
    const float* __restrict__ Vp, const unsigned char* __restrict__ mask,
    float* __restrict__ u, float* __restrict__ ms,
    int d, int mlen, int splits)
{
    extern __shared__ float smf[];
    float* qs = smf;
    float* sc = smf + 512;
    float* ts = smf + 512 + 8 * mlen;

    const int nh = gridDim.x;
    const int h = blockIdx.x, b0 = blockIdx.y << 3, z = blockIdx.z;
    const int base = h << 6;
    const int m0 = z * mlen;
    const int tid = threadIdx.x, lane = tid & 31, wid = tid >> 5;

    for (int i = tid; i < 512; i += 256) {
        int qq = i >> 6, k = i & 63;
        qs[i] = qp[(size_t)(b0 + qq) * d + base + k];
    }
    __syncthreads();

    const float4* qs4 = (const float4*)(qs + (wid << 6));
    const unsigned char* mrow = mask + (size_t)(b0 + wid) * MEM + m0;

    for (int mc = 0; mc < mlen; mc += 64) {
        for (int i = tid; i < 64 * 16; i += 256) {
            int r = i >> 4, c4 = (i & 15) << 2;
            float4 v = *(const float4*)(Kp + (size_t)(m0 + mc + r) * d + base + c4);
            float* dst = ts + r * 65 + c4;
            dst[0] = v.x; dst[1] = v.y; dst[2] = v.z; dst[3] = v.w;
        }
        __syncthreads();
        float acc0 = 0.f, acc1 = 0.f;
        const float* t0 = ts + lane * 65;
        const float* t1 = ts + (lane + 32) * 65;
#pragma unroll
        for (int k4 = 0; k4 < 16; k4++) {
            float4 qv = qs4[k4];
            acc0 += qv.x * t0[k4 * 4] + qv.y * t0[k4 * 4 + 1] + qv.z * t0[k4 * 4 + 2] + qv.w * t0[k4 * 4 + 3];
            acc1 += qv.x * t1[k4 * 4] + qv.y * t1[k4 * 4 + 1] + qv.z * t1[k4 * 4 + 2] + qv.w * t1[k4 * 4 + 3];
        }
        sc[wid * mlen + mc + lane]      = mrow[mc + lane]      ? -1e9f : acc0;
        sc[wid * mlen + mc + 32 + lane] = mrow[mc + 32 + lane] ? -1e9f : acc1;
        __syncthreads();
    }

    float* row = sc + wid * mlen;
    float mx = -1e30f;
    for (int i = lane; i < mlen; i += 32) mx = fmaxf(mx, row[i]);
#pragma unroll
    for (int off = 16; off; off >>= 1) mx = fmaxf(mx, __shfl_xor_sync(0xffffffffu, mx, off));
    float sum = 0.f;
    for (int i = lane; i < mlen; i += 32) {
        float e = __expf(row[i] - mx);
        row[i] = e;
        sum += e;
    }
#pragma unroll
    for (int off = 16; off; off >>= 1) sum += __shfl_xor_sync(0xffffffffu, sum, off);
    if (lane == 0) {
        const int idx = ((b0 + wid) * nh + h) * splits + z;
        ms[idx * 2]     = mx;
        ms[idx * 2 + 1] = sum;
    }

    float acc[8][2] = {};
    for (int mc = 0; mc < mlen; mc += 64) {
        __syncthreads();
        for (int i = tid; i < 64 * 16; i += 256) {
            int r = i >> 4, c4 = (i & 15) << 2;
            float4 v = *(const float4*)(Vp + (size_t)(m0 + mc + r) * d + base + c4);
            float* dst = ts + r * 65 + c4;
            dst[0] = v.x; dst[1] = v.y; dst[2] = v.z; dst[3] = v.w;
        }
        __syncthreads();
        float v0[8], v1[8];
#pragma unroll
        for (int jl = 0; jl < 8; jl++) {
            v0[jl] = ts[(wid * 8 + jl) * 65 + lane];
            v1[jl] = ts[(wid * 8 + jl) * 65 + lane + 32];
        }
        const int jbase = mc + wid * 8;
#pragma unroll
        for (int q = 0; q < 8; q++) {
            float4 pa4 = *(const float4*)(sc + q * mlen + jbase);
            float4 pb4 = *(const float4*)(sc + q * mlen + jbase + 4);
            const float p[8] = {pa4.x, pa4.y, pa4.z, pa4.w, pb4.x, pb4.y, pb4.z, pb4.w};
#pragma unroll
            for (int jl = 0; jl < 8; jl++) {
                acc[q][0] += p[jl] * v0[jl];
                acc[q][1] += p[jl] * v1[jl];
            }
        }
    }

    __syncthreads();
#pragma unroll
    for (int q = 0; q < 8; q++) {
        ts[wid * 512 + q * 64 + lane]      = acc[q][0];
        ts[wid * 512 + q * 64 + lane + 32] = acc[q][1];
    }
    __syncthreads();
    for (int oidx = tid; oidx < 512; oidx += 256) {
        const int q = oidx >> 6, c = oidx & 63;
        float s = 0.f;
#pragma unroll
        for (int w = 0; w < 8; w++) s += ts[w * 512 + oidx];
        u[((size_t)((b0 + q) * nh + h) * splits + z) * 64 + c] = s;
    }
}

__global__ void attn_combine(const float* __restrict__ u, const float* __restrict__ ms,
                             float* __restrict__ o, int d, int nh, int splits)
{
    const int bh = blockIdx.x;
    const int b = bh / nh, h = bh % nh, c = threadIdx.x;
    float M = -1e30f;
    for (int z = 0; z < splits; z++) M = fmaxf(M, ms[(bh * splits + z) * 2]);
    float S = 0.f, O = 0.f;
    for (int z = 0; z < splits; z++) {
        const float w = __expf(ms[(bh * splits + z) * 2] - M);
        S += w * ms[(bh * splits + z) * 2 + 1];
        O += w * u[((size_t)bh * splits + z) * 64 + c];
    }
    o[(size_t)b * d + (h << 6) + c] = O / S;
}

// ======================= per-bundle LayerNorm ==============================
__global__ void __launch_bounds__(256) ln_kernel(
    const float* __restrict__ x, const float* __restrict__ g,
    const float* __restrict__ be, float* __restrict__ out,
    int slotBase, int nslots)
{
    __shared__ float rs[8], rss[8];
    __shared__ float s_mu, s_inv;
    const int bi = blockIdx.x / nslots, slot = slotBase + blockIdx.x % nslots;
    const int rowi = bi * 16 + slot;
    const float4* xr = (const float4*)(x + (size_t)rowi * DLLM);
    const int tid = threadIdx.x, lane = tid & 31, warp = tid >> 5;
    float s = 0.f, ss = 0.f;
    for (int i = tid; i < DLLM / 4; i += 256) {
        float4 v = xr[i];
        s  += v.x + v.y + v.z + v.w;
        ss += v.x * v.x + v.y * v.y + v.z * v.z + v.w * v.w;
    }
#pragma unroll
    for (int off = 16; off; off >>= 1) {
        s  += __shfl_xor_sync(0xffffffffu, s, off);
        ss += __shfl_xor_sync(0xffffffffu, ss, off);
    }
    if (lane == 0) { rs[warp] = s; rss[warp] = ss; }
    __syncthreads();
    if (tid == 0) {
        float S = 0.f, SS = 0.f;
#pragma unroll
        for (int w = 0; w < 8; w++) { S += rs[w]; SS += rss[w]; }
        const float mu = S * (1.0f / DLLM);
        const float var = SS * (1.0f / DLLM) - mu * mu;
        s_mu = mu;
        s_inv = rsqrtf(var + 1e-5f);
    }
    __syncthreads();
    const float mu = s_mu, inv = s_inv;
    const float4* g4 = (const float4*)g;
    const float4* b4 = (const float4*)be;
    float4* outr = (float4*)(out + (size_t)rowi * DLLM);
    for (int i = tid; i < DLLM / 4; i += 256) {
        float4 v = xr[i], gv = g4[i], bv = b4[i];
        float4 r;
        r.x = (v.x - mu) * inv * gv.x + bv.x;
        r.y = (v.y - mu) * inv * gv.y + bv.y;
        r.z = (v.z - mu) * inv * gv.z + bv.z;
        r.w = (v.w - mu) * inv * gv.w + bv.w;
        outr[i] = r;
    }
}

// ======================= streams/events ====================================
struct StreamInit {
    cudaStream_t sA[3], sB[3];
    cudaEvent_t evFork, evKV[3], evD[3];
    StreamInit() {
        for (int i = 0; i < 3; i++) {
            cudaStreamCreateWithFlags(&sA[i], cudaStreamNonBlocking);
            cudaStreamCreateWithFlags(&sB[i], cudaStreamNonBlocking);
            cudaEventCreateWithFlags(&evKV[i], cudaEventDisableTiming);
            cudaEventCreateWithFlags(&evD[i], cudaEventDisableTiming);
        }
        cudaEventCreateWithFlags(&evFork, cudaEventDisableTiming);
    }
};
static StreamInit g_si;

// ======================= host orchestration ================================
extern "C" void kernel_launch(void* const* d_in, const int* in_sizes, int n_in,
                              void* d_out, int out_size)
{
    const float* hidden = (const float*)d_in[0];
    const float* fibers[3] = {(const float*)d_in[1], (const float*)d_in[2], (const float*)d_in[3]};
    const unsigned char* mask = (const unsigned char*)d_in[4];
    const float* Wq[3]    = {(const float*)d_in[5],  (const float*)d_in[7],  (const float*)d_in[9]};
    const float* bq[3]    = {(const float*)d_in[6],  (const float*)d_in[8],  (const float*)d_in[10]};
    const float* Wqkv[3]  = {(const float*)d_in[11], (const float*)d_in[15], (const float*)d_in[19]};
    const float* bqkv[3]  = {(const float*)d_in[12], (const float*)d_in[16], (const float*)d_in[20]};
    const float* Wo[3]    = {(const float*)d_in[13], (const float*)d_in[17], (const float*)d_in[21]};
    const float* bo[3]    = {(const float*)d_in[14], (const float*)d_in[18], (const float*)d_in[22]};
    const float* Wlift[3] = {(const float*)d_in[23], (const float*)d_in[25], (const float*)d_in[27]};
    const float* blift[3] = {(const float*)d_in[24], (const float*)d_in[26], (const float*)d_in[28]};
    const float* lng = (const float*)d_in[29];
    const float* lnb = (const float*)d_in[30];

    const int ds[3]       = {256, 512, 1024};
    const int nhs[3]      = {4, 8, 16};
    const int slots[3]    = {4, 8, 4};
    const int slotBase[3] = {0, 4, 12};
    const int splits[3]   = {8, 4, 2};
    const size_t kvfOff[3]= {0, 1048576, 3145728};
    const size_t bOff[3]  = {0, 16384, 49152};
    const size_t uOff[3]  = {0, 131072, 262144};
    const size_t msOff[3] = {0, 4096, 8192};

    float *prefix, *kvf, *qb, *qp, *oo, *o2, *uu, *msb;
    cudaGetSymbolAddress((void**)&prefix, g_prefix);
    cudaGetSymbolAddress((void**)&kvf, g_kvf);
    cudaGetSymbolAddress((void**)&qb, g_qb);
    cudaGetSymbolAddress((void**)&qp, g_qp);
    cudaGetSymbolAddress((void**)&oo, g_o);
    cudaGetSymbolAddress((void**)&o2, g_o2);
    cudaGetSymbolAddress((void**)&uu, g_u);
    cudaGetSymbolAddress((void**)&msb, g_ms);

    cudaFuncSetAttribute(hmma_f32, cudaFuncAttributeMaxDynamicSharedMemorySize, HMMA_SMEM);
    cudaFuncSetAttribute(hmma_kv16, cudaFuncAttributeMaxDynamicSharedMemorySize, KV16_SMEM);
    cudaFuncSetAttribute(attn_split, cudaFuncAttributeMaxDynamicSharedMemorySize,
                         (512 + 8 * 1024 + 4160) * 4);
    // max smem carveout: let big launches run >1 CTA/SM
    cudaFuncSetAttribute(hmma_f32, cudaFuncAttributePreferredSharedMemoryCarveout, 100);
    cudaFuncSetAttribute(hmma_kv16, cudaFuncAttributePreferredSharedMemoryCarveout, 100);
    cudaFuncSetAttribute(attn_split, cudaFuncAttributePreferredSharedMemoryCarveout, 100);

    init_bias<<<(114688 + 255) / 256, 256>>>(qb, qp, o2,
        bq[0], bq[1], bq[2], bqkv[0], bqkv[1], bqkv[2], bo[0], bo[1], bo[2]);
    cudaEventRecord(g_si.evFork, 0);

    for (int b = 0; b < 3; b++) {
        const int d = ds[b], nh = nhs[b], s = slots[b], sp = splits[b];
        const int mlen = MEM / sp;
        const int attn_smem = (512 + 8 * mlen + 4160) * 4;
        cudaStream_t A = g_si.sA[b], Bs = g_si.sB[b];

        // ---- stream A: KV projection (fp16 single-pass) ----
        cudaStreamWaitEvent(A, g_si.evFork, 0);
        hmma_kv16<<<dim3(d / 64, MEM / 128, 2), 256, KV16_SMEM, A>>>(
            fibers[b], Wqkv[b] + (size_t)d * d, bqkv[b] + d, d,
            kvf + kvfOff[b], d, (long long)MEM * d,
            (long long)d * d, d);
        cudaEventRecord(g_si.evKV[b], A);

        // ---- stream B: q chain -> attention -> out-proj -> lift -> LN ----
        cudaStreamWaitEvent(Bs, g_si.evFork, 0);
        hmma_f32<<<dim3(d / 64, 1, 16), 256, HMMA_SMEM, Bs>>>(
            hidden, Wq[b], nullptr, 0,
            qb + bOff[b], d, 0,
            0, DLLM, DLLM, BATCH, BATCH, 256, 0, 1.0f);
        hmma_f32<<<dim3(d / 64, 1, 4), 256, HMMA_SMEM, Bs>>>(
            qb + bOff[b], Wqkv[b], nullptr, 0,
            qp + bOff[b], d, 0,
            0, d, d, BATCH, BATCH, d / 4, 0, 0.125f);
        cudaStreamWaitEvent(Bs, g_si.evKV[b], 0);
        attn_split<<<dim3(nh, BATCH / 8, sp), 256, attn_smem, Bs>>>(
            qp + bOff[b], kvf + kvfOff[b], kvf + kvfOff[b] + (size_t)MEM * d, mask,
            uu + uOff[b], msb + msOff[b], d, mlen, sp);
        attn_combine<<<BATCH * nh, 64, 0, Bs>>>(
            uu + uOff[b], msb + msOff[b], oo + bOff[b], d, nh, sp);
        hmma_f32<<<dim3(d / 64, 1, 4), 256, HMMA_SMEM, Bs>>>(
            oo + bOff[b], Wo[b], nullptr, 0,
            o2 + bOff[b], d, 0,
            0, d, d, BATCH, BATCH, d / 4, 0, 1.0f);
        hmma_f32<<<dim3(DLLM / 64, 1, s), 256, HMMA_SMEM, Bs>>>(
            o2 + bOff[b], Wlift[b], blift[b], DLLM,
            prefix + (size_t)slotBase[b] * DLLM, 16 * DLLM, DLLM,
            (long long)d * DLLM, d, DLLM, BATCH, BATCH, 0, 1, 1.0f);
        ln_kernel<<<BATCH * s, 256, 0, Bs>>>(
            prefix, lng, lnb, (float*)d_out, slotBase[b], s);
        cudaEventRecord(g_si.evD[b], Bs);
    }

    for (int b = 0; b < 3; b++) cudaStreamWaitEvent(0, g_si.evD[b], 0);
}

// round 16
// speedup vs baseline: 1.5841x; 1.1842x over previous
#include <cuda_runtime.h>
#include <cuda_bf16.h>
#include <cuda_fp16.h>
#include <cstdint>

// ---------------------------------------------------------------------------
// CrossBundleAttention — fp16 single-pass KV-proj + lift, bf16 hi/lo elsewhere
// B=64, M=2048, D_LLM=4096, bundles: (d=256,nh=4,s=4) (512,8,8) (1024,16,4)
// ---------------------------------------------------------------------------

#define BATCH 64
#define MEM   2048
#define DLLM  4096
#define STR   72

// ======================= scratch (device globals) ==========================
__device__ float g_prefix[4194304];
__device__ float g_kvf[7340032];
__device__ float g_qb[114688], g_qp[114688], g_o[114688], g_o2[114688];
__device__ float g_u[393216];
__device__ float g_ms[24576];

// ======================= MMA helpers =======================================
__device__ __forceinline__ void mma16816(float* c, const uint32_t* a, const uint32_t* b) {
    asm volatile(
        "mma.sync.aligned.m16n8k16.row.col.f32.bf16.bf16.f32 "
        "{%0,%1,%2,%3}, {%4,%5,%6,%7}, {%8,%9}, {%0,%1,%2,%3};"
        : "+f"(c[0]), "+f"(c[1]), "+f"(c[2]), "+f"(c[3])
        : "r"(a[0]), "r"(a[1]), "r"(a[2]), "r"(a[3]), "r"(b[0]), "r"(b[1]));
}
__device__ __forceinline__ void mma16816h(float* c, const uint32_t* a, const uint32_t* b) {
    asm volatile(
        "mma.sync.aligned.m16n8k16.row.col.f32.f16.f16.f32 "
        "{%0,%1,%2,%3}, {%4,%5,%6,%7}, {%8,%9}, {%0,%1,%2,%3};"
        : "+f"(c[0]), "+f"(c[1]), "+f"(c[2]), "+f"(c[3])
        : "r"(a[0]), "r"(a[1]), "r"(a[2]), "r"(a[3]), "r"(b[0]), "r"(b[1]));
}
__device__ __forceinline__ void ldm4(uint32_t* r, const void* p) {
    uint32_t a = (uint32_t)__cvta_generic_to_shared(p);
    asm volatile("ldmatrix.sync.aligned.m8n8.x4.shared.b16 {%0,%1,%2,%3}, [%4];"
        : "=r"(r[0]), "=r"(r[1]), "=r"(r[2]), "=r"(r[3]) : "r"(a));
}
__device__ __forceinline__ uint32_t pack2(__nv_bfloat16 a, __nv_bfloat16 b) {
    __nv_bfloat162 p(a, b);
    return *(uint32_t*)&p;
}
__device__ __forceinline__ void cvt4(float4 v, uint2& hh, uint2& ll) {
    __nv_bfloat16 h0 = __float2bfloat16(v.x), h1 = __float2bfloat16(v.y);
    __nv_bfloat16 h2 = __float2bfloat16(v.z), h3 = __float2bfloat16(v.w);
    __nv_bfloat16 l0 = __float2bfloat16(v.x - __bfloat162float(h0));
    __nv_bfloat16 l1 = __float2bfloat16(v.y - __bfloat162float(h1));
    __nv_bfloat16 l2 = __float2bfloat16(v.z - __bfloat162float(h2));
    __nv_bfloat16 l3 = __float2bfloat16(v.w - __bfloat162float(h3));
    hh.x = pack2(h0, h1); hh.y = pack2(h2, h3);
    ll.x = pack2(l0, l1); ll.y = pack2(l2, l3);
}
__device__ __forceinline__ uint2 cvt4h(float4 v) {
    __half2 p0 = __floats2half2_rn(v.x, v.y);
    __half2 p1 = __floats2half2_rn(v.z, v.w);
    uint2 r;
    r.x = *(uint32_t*)&p0;
    r.y = *(uint32_t*)&p1;
    return r;
}

#define HMMA_SMEM ((2 * 128 * STR + 2 * 64 * STR) * 2)   // 55296 B
#define H16_SMEM  ((128 * STR + 64 * STR) * 2)           // 27648 B

// ---------------------------------------------------------------------------
// bf16 hi/lo HMMA GEMM (chain GEMMs; R11 path).
// ---------------------------------------------------------------------------
__global__ void __launch_bounds__(256) hmma_f32(
    const float* __restrict__ A, const float* __restrict__ Bm,
    const float* __restrict__ bias, long long bias_zstr,
    float* __restrict__ C, long long c_row, long long c_zstr,
    long long b_zstr, int K, int ldb, int a_rows, int m_valid,
    int kslice, int transB, float alpha)
{
    extern __shared__ __nv_bfloat16 sm[];
    __nv_bfloat16* Ah = sm;
    __nv_bfloat16* Al = sm + 128 * STR;
    __nv_bfloat16* Bh = sm + 2 * 128 * STR;
    __nv_bfloat16* Bl = Bh + 64 * STR;

    const int tid = threadIdx.x, wid = tid >> 5, lane = tid & 31;
    const int nBase = blockIdx.x << 6, mBase = blockIdx.y << 7, z = blockIdx.z;

    int k0s, k0e;
    const float* bp;
    if (kslice) {
        k0s = z * kslice; k0e = k0s + kslice;
        bp = Bm;
    } else {
        k0s = 0; k0e = K;
        bp = Bm + (size_t)z * b_zstr;
    }

    const int mW = (wid >> 1) << 5;
    const int nW = (wid & 1) << 5;
    const int grp = lane >> 2, qid = lane & 3;
    const int lane7 = lane & 7, l8 = (lane >> 3) & 1, l16 = (lane >> 4) & 1;
    const int aOff = (lane7 + l8 * 8) * STR + l16 * 8;
    const int bOff = (lane7 + l16 * 8) * STR + l8 * 8;

    const int ar = tid >> 4, ac4 = (tid & 15) << 2;
    float acc[2][4][4] = {};
    float4 pa[8], pb[4];

    auto loadA = [&](int k0) {
#pragma unroll
        for (int it = 0; it < 8; it++) {
            const int r = ar + it * 16;
            if (mBase + r < a_rows)
                pa[it] = *(const float4*)(A + (size_t)(mBase + r) * K + k0 + ac4);
            else
                pa[it] = make_float4(0.f, 0.f, 0.f, 0.f);
        }
    };
    auto loadB = [&](int k0) {
        if (!transB) {
#pragma unroll
            for (int it = 0; it < 4; it++) {
                const int r = ar + it * 16;
                pb[it] = *(const float4*)(bp + (size_t)(nBase + r) * K + k0 + ac4);
            }
        } else {
#pragma unroll
            for (int it = 0; it < 4; it++) {
                const int kr = ar + it * 16;
                pb[it] = *(const float4*)(bp + (size_t)(k0 + kr) * ldb + nBase + ac4);
            }
        }
    };
    auto storeAB = [&]() {
#pragma unroll
        for (int it = 0; it < 8; it++) {
            const int r = ar + it * 16;
            uint2 hh, ll;
            cvt4(pa[it], hh, ll);
            *(uint2*)(Ah + r * STR + ac4) = hh;
            *(uint2*)(Al + r * STR + ac4) = ll;
        }
        if (!transB) {
#pragma unroll
            for (int it = 0; it < 4; it++) {
                const int r = ar + it * 16;
                uint2 hh, ll;
                cvt4(pb[it], hh, ll);
                *(uint2*)(Bh + r * STR + ac4) = hh;
                *(uint2*)(Bl + r * STR + ac4) = ll;
            }
        } else {
#pragma unroll
            for (int it = 0; it < 4; it++) {
                const int kr = ar + it * 16;
                const float vv[4] = {pb[it].x, pb[it].y, pb[it].z, pb[it].w};
#pragma unroll
                for (int j = 0; j < 4; j++) {
                    __nv_bfloat16 h = __float2bfloat16(vv[j]);
                    Bh[(ac4 + j) * STR + kr] = h;
                    Bl[(ac4 + j) * STR + kr] = __float2bfloat16(vv[j] - __bfloat162float(h));
                }
            }
        }
    };

    loadA(k0s);
    loadB(k0s);

    for (int k0 = k0s; k0 < k0e; k0 += 64) {
        __syncthreads();
        storeAB();
        __syncthreads();
        if (k0 + 64 < k0e) {
            loadA(k0 + 64);
            loadB(k0 + 64);
        }

#pragma unroll
        for (int kk = 0; kk < 4; kk++) {
            const int kc = kk << 4;
            uint32_t ah[2][4], al[2][4], bhf[4][2], blf[4][2], t4[4];
#pragma unroll
            for (int mi = 0; mi < 2; mi++) {
                ldm4(ah[mi], Ah + (mW + mi * 16) * STR + kc + aOff);
                ldm4(al[mi], Al + (mW + mi * 16) * STR + kc + aOff);
            }
#pragma unroll
            for (int p = 0; p < 2; p++) {
                ldm4(t4, Bh + (nW + p * 16) * STR + kc + bOff);
                bhf[p * 2][0] = t4[0]; bhf[p * 2][1] = t4[1];
                bhf[p * 2 + 1][0] = t4[2]; bhf[p * 2 + 1][1] = t4[3];
                ldm4(t4, Bl + (nW + p * 16) * STR + kc + bOff);
                blf[p * 2][0] = t4[0]; blf[p * 2][1] = t4[1];
                blf[p * 2 + 1][0] = t4[2]; blf[p * 2 + 1][1] = t4[3];
            }
#pragma unroll
            for (int mi = 0; mi < 2; mi++)
#pragma unroll
                for (int ni = 0; ni < 4; ni++) {
                    mma16816(acc[mi][ni], ah[mi], bhf[ni]);
                    mma16816(acc[mi][ni], ah[mi], blf[ni]);
                    mma16816(acc[mi][ni], al[mi], bhf[ni]);
                }
        }
    }

    if (kslice) {
#pragma unroll
        for (int mi = 0; mi < 2; mi++) {
            const int r0 = mBase + mW + mi * 16 + grp;
#pragma unroll
            for (int ni = 0; ni < 4; ni++) {
                const int c = nBase + nW + ni * 8 + qid * 2;
                if (r0 < m_valid) {
                    atomicAdd(C + (size_t)r0 * c_row + c,     alpha * acc[mi][ni][0]);
                    atomicAdd(C + (size_t)r0 * c_row + c + 1, alpha * acc[mi][ni][1]);
                }
                if (r0 + 8 < m_valid) {
                    atomicAdd(C + (size_t)(r0 + 8) * c_row + c,     alpha * acc[mi][ni][2]);
                    atomicAdd(C + (size_t)(r0 + 8) * c_row + c + 1, alpha * acc[mi][ni][3]);
                }
            }
        }
    } else {
        float* Cz = C + (size_t)z * c_zstr;
        const float* brow = bias + (size_t)z * bias_zstr;
#pragma unroll
        for (int mi = 0; mi < 2; mi++) {
            const int r0 = mBase + mW + mi * 16 + grp;
#pragma unroll
            for (int ni = 0; ni < 4; ni++) {
                const int c = nBase + nW + ni * 8 + qid * 2;
                const float b0 = brow[c], b1 = brow[c + 1];
                if (r0 < m_valid) {
                    float2 v = {acc[mi][ni][0] + b0, acc[mi][ni][1] + b1};
                    *(float2*)(Cz + (size_t)r0 * c_row + c) = v;
                }
                if (r0 + 8 < m_valid) {
                    float2 v = {acc[mi][ni][2] + b0, acc[mi][ni][3] + b1};
                    *(float2*)(Cz + (size_t)(r0 + 8) * c_row + c) = v;
                }
            }
        }
    }
}

// ---------------------------------------------------------------------------
// fp16 single-pass GEMM (KV projection + lift).
// transB==0: B (N,K) row-major, z selects slice via b_zstr.
// transB==1: B (K,ldb) row-major, z selects slice via b_zstr (lift slots).
// C[z][m][n] = acc + bias[z][n]; rows >= m_valid not stored; A rows >= a_rows zero.
// ---------------------------------------------------------------------------
__global__ void __launch_bounds__(256) hmma_h16(
    const float* __restrict__ A, const float* __restrict__ Bm,
    const float* __restrict__ bias, long long bias_zstr,
    float* __restrict__ C, long long c_row, long long c_zstr,
    long long b_zstr, int K, int ldb, int a_rows, int m_valid, int transB)
{
    extern __shared__ __half smh[];
    __half* Ah = smh;
    __half* Bh = smh + 128 * STR;

    const int tid = threadIdx.x, wid = tid >> 5, lane = tid & 31;
    const int nBase = blockIdx.x << 6, mBase = blockIdx.y << 7, z = blockIdx.z;
    const float* bp = Bm + (size_t)z * b_zstr;

    const int mW = (wid >> 1) << 5;
    const int nW = (wid & 1) << 5;
    const int grp = lane >> 2, qid = lane & 3;
    const int lane7 = lane & 7, l8 = (lane >> 3) & 1, l16 = (lane >> 4) & 1;
    const int aOff = (lane7 + l8 * 8) * STR + l16 * 8;
    const int bOff = (lane7 + l16 * 8) * STR + l8 * 8;

    const int ar = tid >> 4, ac4 = (tid & 15) << 2;
    float acc[2][4][4] = {};
    float4 pa[8], pb[4];

    auto loadA = [&](int k0) {
#pragma unroll
        for (int it = 0; it < 8; it++) {
            const int r = ar + it * 16;
            if (mBase + r < a_rows)
                pa[it] = *(const float4*)(A + (size_t)(mBase + r) * K + k0 + ac4);
            else
                pa[it] = make_float4(0.f, 0.f, 0.f, 0.f);
        }
    };
    auto loadB = [&](int k0) {
        if (!transB) {
#pragma unroll
            for (int it = 0; it < 4; it++) {
                const int r = ar + it * 16;
                pb[it] = *(const float4*)(bp + (size_t)(nBase + r) * K + k0 + ac4);
            }
        } else {
#pragma unroll
            for (int it = 0; it < 4; it++) {
                const int kr = ar + it * 16;
                pb[it] = *(const float4*)(bp + (size_t)(k0 + kr) * ldb + nBase + ac4);
            }
        }
    };
    auto storeAB = [&]() {
#pragma unroll
        for (int it = 0; it < 8; it++)
            *(uint2*)(Ah + (ar + it * 16) * STR + ac4) = cvt4h(pa[it]);
        if (!transB) {
#pragma unroll
            for (int it = 0; it < 4; it++)
                *(uint2*)(Bh + (ar + it * 16) * STR + ac4) = cvt4h(pb[it]);
        } else {
#pragma unroll
            for (int it = 0; it < 4; it++) {
                const int kr = ar + it * 16;
                const float vv[4] = {pb[it].x, pb[it].y, pb[it].z, pb[it].w};
#pragma unroll
                for (int j = 0; j < 4; j++)
                    Bh[(ac4 + j) * STR + kr] = __float2half_rn(vv[j]);
            }
        }
    };

    loadA(0);
    loadB(0);

    for (int k0 = 0; k0 < K; k0 += 64) {
        __syncthreads();
        storeAB();
        __syncthreads();
        if (k0 + 64 < K) {
            loadA(k0 + 64);
            loadB(k0 + 64);
        }

#pragma unroll
        for (int kk = 0; kk < 4; kk++) {
            const int kc = kk << 4;
            uint32_t ah[2][4], bhf[4][2], t4[4];
#pragma unroll
            for (int mi = 0; mi < 2; mi++)
                ldm4(ah[mi], Ah + (mW + mi * 16) * STR + kc + aOff);
#pragma unroll
            for (int p = 0; p < 2; p++) {
                ldm4(t4, Bh + (nW + p * 16) * STR + kc + bOff);
                bhf[p * 2][0] = t4[0]; bhf[p * 2][1] = t4[1];
                bhf[p * 2 + 1][0] = t4[2]; bhf[p * 2 + 1][1] = t4[3];
            }
#pragma unroll
            for (int mi = 0; mi < 2; mi++)
#pragma unroll
                for (int ni = 0; ni < 4; ni++)
                    mma16816h(acc[mi][ni], ah[mi], bhf[ni]);
        }
    }

    float* Cz = C + (size_t)z * c_zstr;
    const float* brow = bias + (size_t)z * bias_zstr;
#pragma unroll
    for (int mi = 0; mi < 2; mi++) {
        const int r0 = mBase + mW + mi * 16 + grp;
#pragma unroll
        for (int ni = 0; ni < 4; ni++) {
            const int c = nBase + nW + ni * 8 + qid * 2;
            const float b0 = brow[c], b1 = brow[c + 1];
            if (r0 < m_valid) {
                float2 v = {acc[mi][ni][0] + b0, acc[mi][ni][1] + b1};
                *(float2*)(Cz + (size_t)r0 * c_row + c) = v;
            }
            if (r0 + 8 < m_valid) {
                float2 v = {acc[mi][ni][2] + b0, acc[mi][ni][3] + b1};
                *(float2*)(Cz + (size_t)(r0 + 8) * c_row + c) = v;
            }
        }
    }
}

// =============== graph root: fill qb/qp/o2 with (scaled) biases =============
__global__ void init_bias(float* __restrict__ qb, float* __restrict__ qp,
                          float* __restrict__ o2,
                          const float* bq0, const float* bq1, const float* bq2,
                          const float* bi0, const float* bi1, const float* bi2,
                          const float* bo0, const float* bo1, const float* bo2)
{
    const int i = blockIdx.x * 256 + threadIdx.x;
    if (i >= 114688) return;
    int n;
    const float *bqv, *biv, *bov;
    if (i < 16384)       { n = i & 255;             bqv = bq0; biv = bi0; bov = bo0; }
    else if (i < 49152)  { n = (i - 16384) & 511;   bqv = bq1; biv = bi1; bov = bo1; }
    else                 { n = (i - 49152) & 1023;  bqv = bq2; biv = bi2; bov = bo2; }
    qb[i] = bqv[n];
    qp[i] = 0.125f * biv[n];
    o2[i] = bov[n];
}

// ======================= split-KV batched attention ========================
__global__ void __launch_bounds__(256) attn_split(
    const float* __restrict__ qp, const float* __restrict__ Kp,
    const float* __restrict__ Vp, const unsigned char* __restrict__ mask,
    float* __restrict__ u, float* __restrict__ ms,
    int d, int mlen, int splits)
{
    extern __shared__ float smf[];
    float* qs = smf;
    float* sc = smf + 512;
    float* ts = smf + 512 + 8 * mlen;

    const int nh = gridDim.x;
    const int h = blockIdx.x, b0 = blockIdx.y << 3, z = blockIdx.z;
    const int base = h << 6;
    const int m0 = z * mlen;
    const int tid = threadIdx.x, lane = tid & 31, wid = tid >> 5;

    for (int i = tid; i < 512; i += 256) {
        int qq = i >> 6, k = i & 63;
        qs[i] = qp[(size_t)(b0 + qq) * d + base + k];
    }
    __syncthreads();

    const float4* qs4 = (const float4*)(qs + (wid << 6));
    const unsigned char* mrow = mask + (size_t)(b0 + wid) * MEM + m0;

    for (int mc = 0; mc < mlen; mc += 64) {
        for (int i = tid; i < 64 * 16; i += 256) {
            int r = i >> 4, c4 = (i & 15) << 2;
            float4 v = *(const float4*)(Kp + (size_t)(m0 + mc + r) * d + base + c4);
            float* dst = ts + r * 65 + c4;
            dst[0] = v.x; dst[1] = v.y; dst[2] = v.z; dst[3] = v.w;
        }
        __syncthreads();
        float acc0 = 0.f, acc1 = 0.f;
        const float* t0 = ts + lane * 65;
        const float* t1 = ts + (lane + 32) * 65;
#pragma unroll
        for (int k4 = 0; k4 < 16; k4++) {
            float4 qv = qs4[k4];
            acc0 += qv.x * t0[k4 * 4] + qv.y * t0[k4 * 4 + 1] + qv.z * t0[k4 * 4 + 2] + qv.w * t0[k4 * 4 + 3];
            acc1 += qv.x * t1[k4 * 4] + qv.y * t1[k4 * 4 + 1] + qv.z * t1[k4 * 4 + 2] + qv.w * t1[k4 * 4 + 3];
        }
        sc[wid * mlen + mc + lane]      = mrow[mc + lane]      ? -1e9f : acc0;
        sc[wid * mlen + mc + 32 + lane] = mrow[mc + 32 + lane] ? -1e9f : acc1;
        __syncthreads();
    }

    float* row = sc + wid * mlen;
    float mx = -1e30f;
    for (int i = lane; i < mlen; i += 32) mx = fmaxf(mx, row[i]);
#pragma unroll
    for (int off = 16; off; off >>= 1) mx = fmaxf(mx, __shfl_xor_sync(0xffffffffu, mx, off));
    float sum = 0.f;
    for (int i = lane; i < mlen; i += 32) {
        float e = __expf(row[i] - mx);
        row[i] = e;
        sum += e;
    }
#pragma unroll
    for (int off = 16; off; off >>= 1) sum += __shfl_xor_sync(0xffffffffu, sum, off);
    if (lane == 0) {
        const int idx = ((b0 + wid) * nh + h) * splits + z;
        ms[idx * 2]     = mx;
        ms[idx * 2 + 1] = sum;
    }

    float acc[8][2] = {};
    for (int mc = 0; mc < mlen; mc += 64) {
        __syncthreads();
        for (int i = tid; i < 64 * 16; i += 256) {
            int r = i >> 4, c4 = (i & 15) << 2;
            float4 v = *(const float4*)(Vp + (size_t)(m0 + mc + r) * d + base + c4);
            float* dst = ts + r * 65 + c4;
            dst[0] = v.x; dst[1] = v.y; dst[2] = v.z; dst[3] = v.w;
        }
        __syncthreads();
        float v0[8], v1[8];
#pragma unroll
        for (int jl = 0; jl < 8; jl++) {
            v0[jl] = ts[(wid * 8 + jl) * 65 + lane];
            v1[jl] = ts[(wid * 8 + jl) * 65 + lane + 32];
        }
        const int jbase = mc + wid * 8;
#pragma unroll
        for (int q = 0; q < 8; q++) {
            float4 pa4 = *(const float4*)(sc + q * mlen + jbase);
            float4 pb4 = *(const float4*)(sc + q * mlen + jbase + 4);
            const float p[8] = {pa4.x, pa4.y, pa4.z, pa4.w, pb4.x, pb4.y, pb4.z, pb4.w};
#pragma unroll
            for (int jl = 0; jl < 8; jl++) {
                acc[q][0] += p[jl] * v0[jl];
                acc[q][1] += p[jl] * v1[jl];
            }
        }
    }

    __syncthreads();
#pragma unroll
    for (int q = 0; q < 8; q++) {
        ts[wid * 512 + q * 64 + lane]      = acc[q][0];
        ts[wid * 512 + q * 64 + lane + 32] = acc[q][1];
    }
    __syncthreads();
    for (int oidx = tid; oidx < 512; oidx += 256) {
        const int q = oidx >> 6, c = oidx & 63;
        float s = 0.f;
#pragma unroll
        for (int w = 0; w < 8; w++) s += ts[w * 512 + oidx];
        u[((size_t)((b0 + q) * nh + h) * splits + z) * 64 + c] = s;
    }
}

__global__ void attn_combine(const float* __restrict__ u, const float* __restrict__ ms,
                             float* __restrict__ o, int d, int nh, int splits)
{
    const int bh = blockIdx.x;
    const int b = bh / nh, h = bh % nh, c = threadIdx.x;
    float M = -1e30f;
    for (int z = 0; z < splits; z++) M = fmaxf(M, ms[(bh * splits + z) * 2]);
    float S = 0.f, O = 0.f;
    for (int z = 0; z < splits; z++) {
        const float w = __expf(ms[(bh * splits + z) * 2] - M);
        S += w * ms[(bh * splits + z) * 2 + 1];
        O += w * u[((size_t)bh * splits + z) * 64 + c];
    }
    o[(size_t)b * d + (h << 6) + c] = O / S;
}

// ======================= per-bundle LayerNorm ==============================
__global__ void __launch_bounds__(256) ln_kernel(
    const float* __restrict__ x, const float* __restrict__ g,
    const float* __restrict__ be, float* __restrict__ out,
    int slotBase, int nslots)
{
    __shared__ float rs[8], rss[8];
    __shared__ float s_mu, s_inv;
    const int bi = blockIdx.x / nslots, slot = slotBase + blockIdx.x % nslots;
    const int rowi = bi * 16 + slot;
    const float4* xr = (const float4*)(x + (size_t)rowi * DLLM);
    const int tid = threadIdx.x, lane = tid & 31, warp = tid >> 5;
    float s = 0.f, ss = 0.f;
    for (int i = tid; i < DLLM / 4; i += 256) {
        float4 v = xr[i];
        s  += v.x + v.y + v.z + v.w;
        ss += v.x * v.x + v.y * v.y + v.z * v.z + v.w * v.w;
    }
#pragma unroll
    for (int off = 16; off; off >>= 1) {
        s  += __shfl_xor_sync(0xffffffffu, s, off);
        ss += __shfl_xor_sync(0xffffffffu, ss, off);
    }
    if (lane == 0) { rs[warp] = s; rss[warp] = ss; }
    __syncthreads();
    if (tid == 0) {
        float S = 0.f, SS = 0.f;
#pragma unroll
        for (int w = 0; w < 8; w++) { S += rs[w]; SS += rss[w]; }
        const float mu = S * (1.0f / DLLM);
        const float var = SS * (1.0f / DLLM) - mu * mu;
        s_mu = mu;
        s_inv = rsqrtf(var + 1e-5f);
    }
    __syncthreads();
    const float mu = s_mu, inv = s_inv;
    const float4* g4 = (const float4*)g;
    const float4* b4 = (const float4*)be;
    float4* outr = (float4*)(out + (size_t)rowi * DLLM);
    for (int i = tid; i < DLLM / 4; i += 256) {
        float4 v = xr[i], gv = g4[i], bv = b4[i];
        float4 r;
        r.x = (v.x - mu) * inv * gv.x + bv.x;
        r.y = (v.y - mu) * inv * gv.y + bv.y;
        r.z = (v.z - mu) * inv * gv.z + bv.z;
        r.w = (v.w - mu) * inv * gv.w + bv.w;
        outr[i] = r;
    }
}

// ======================= streams/events ====================================
struct StreamInit {
    cudaStream_t sA[3], sB[3];
    cudaEvent_t evFork, evKV[3], evD[3];
    StreamInit() {
        for (int i = 0; i < 3; i++) {
            cudaStreamCreateWithFlags(&sA[i], cudaStreamNonBlocking);
            cudaStreamCreateWithFlags(&sB[i], cudaStreamNonBlocking);
            cudaEventCreateWithFlags(&evKV[i], cudaEventDisableTiming);
            cudaEventCreateWithFlags(&evD[i], cudaEventDisableTiming);
        }
        cudaEventCreateWithFlags(&evFork, cudaEventDisableTiming);
    }
};
static StreamInit g_si;

// ======================= host orchestration ================================
extern "C" void kernel_launch(void* const* d_in, const int* in_sizes, int n_in,
                              void* d_out, int out_size)
{
    const float* hidden = (const float*)d_in[0];
    const float* fibers[3] = {(const float*)d_in[1], (const float*)d_in[2], (const float*)d_in[3]};
    const unsigned char* mask = (const unsigned char*)d_in[4];
    const float* Wq[3]    = {(const float*)d_in[5],  (const float*)d_in[7],  (const float*)d_in[9]};
    const float* bq[3]    = {(const float*)d_in[6],  (const float*)d_in[8],  (const float*)d_in[10]};
    const float* Wqkv[3]  = {(const float*)d_in[11], (const float*)d_in[15], (const float*)d_in[19]};
    const float* bqkv[3]  = {(const float*)d_in[12], (const float*)d_in[16], (const float*)d_in[20]};
    const float* Wo[3]    = {(const float*)d_in[13], (const float*)d_in[17], (const float*)d_in[21]};
    const float* bo[3]    = {(const float*)d_in[14], (const float*)d_in[18], (const float*)d_in[22]};
    const float* Wlift[3] = {(const float*)d_in[23], (const float*)d_in[25], (const float*)d_in[27]};
    const float* blift[3] = {(const float*)d_in[24], (const float*)d_in[26], (const float*)d_in[28]};
    const float* lng = (const float*)d_in[29];
    const float* lnb = (const float*)d_in[30];

    const int ds[3]       = {256, 512, 1024};
    const int nhs[3]      = {4, 8, 16};
    const int slots[3]    = {4, 8, 4};
    const int slotBase[3] = {0, 4, 12};
    const int splits[3]   = {8, 4, 2};
    const size_t kvfOff[3]= {0, 1048576, 3145728};
    const size_t bOff[3]  = {0, 16384, 49152};
    const size_t uOff[3]  = {0, 131072, 262144};
    const size_t msOff[3] = {0, 4096, 8192};

    float *prefix, *kvf, *qb, *qp, *oo, *o2, *uu, *msb;
    cudaGetSymbolAddress((void**)&prefix, g_prefix);
    cudaGetSymbolAddress((void**)&kvf, g_kvf);
    cudaGetSymbolAddress((void**)&qb, g_qb);
    cudaGetSymbolAddress((void**)&qp, g_qp);
    cudaGetSymbolAddress((void**)&oo, g_o);
    cudaGetSymbolAddress((void**)&o2, g_o2);
    cudaGetSymbolAddress((void**)&uu, g_u);
    cudaGetSymbolAddress((void**)&msb, g_ms);

    cudaFuncSetAttribute(hmma_f32, cudaFuncAttributeMaxDynamicSharedMemorySize, HMMA_SMEM);
    cudaFuncSetAttribute(hmma_h16, cudaFuncAttributeMaxDynamicSharedMemorySize, H16_SMEM);
    cudaFuncSetAttribute(attn_split, cudaFuncAttributeMaxDynamicSharedMemorySize,
                         (512 + 8 * 1024 + 4160) * 4);
    cudaFuncSetAttribute(hmma_f32, cudaFuncAttributePreferredSharedMemoryCarveout, 100);
    cudaFuncSetAttribute(hmma_h16, cudaFuncAttributePreferredSharedMemoryCarveout, 100);
    cudaFuncSetAttribute(attn_split, cudaFuncAttributePreferredSharedMemoryCarveout, 100);

    init_bias<<<(114688 + 255) / 256, 256>>>(qb, qp, o2,
        bq[0], bq[1], bq[2], bqkv[0], bqkv[1], bqkv[2], bo[0], bo[1], bo[2]);
    cudaEventRecord(g_si.evFork, 0);

    for (int b = 0; b < 3; b++) {
        const int d = ds[b], nh = nhs[b], s = slots[b], sp = splits[b];
        const int mlen = MEM / sp;
        const int attn_smem = (512 + 8 * mlen + 4160) * 4;
        cudaStream_t A = g_si.sA[b], Bs = g_si.sB[b];

        // ---- stream A: KV projection (fp16 single-pass) ----
        cudaStreamWaitEvent(A, g_si.evFork, 0);
        hmma_h16<<<dim3(d / 64, MEM / 128, 2), 256, H16_SMEM, A>>>(
            fibers[b], Wqkv[b] + (size_t)d * d, bqkv[b] + d, d,
            kvf + kvfOff[b], d, (long long)MEM * d,
            (long long)d * d, d, d, MEM, MEM, 0);
        cudaEventRecord(g_si.evKV[b], A);

        // ---- stream B: q chain -> attention -> out-proj -> lift -> LN ----
        cudaStreamWaitEvent(Bs, g_si.evFork, 0);
        hmma_f32<<<dim3(d / 64, 1, 16), 256, HMMA_SMEM, Bs>>>(
            hidden, Wq[b], nullptr, 0,
            qb + bOff[b], d, 0,
            0, DLLM, DLLM, BATCH, BATCH, 256, 0, 1.0f);
        hmma_f32<<<dim3(d / 64, 1, 4), 256, HMMA_SMEM, Bs>>>(
            qb + bOff[b], Wqkv[b], nullptr, 0,
            qp + bOff[b], d, 0,
            0, d, d, BATCH, BATCH, d / 4, 0, 0.125f);
        cudaStreamWaitEvent(Bs, g_si.evKV[b], 0);
        attn_split<<<dim3(nh, BATCH / 8, sp), 256, attn_smem, Bs>>>(
            qp + bOff[b], kvf + kvfOff[b], kvf + kvfOff[b] + (size_t)MEM * d, mask,
            uu + uOff[b], msb + msOff[b], d, mlen, sp);
        attn_combine<<<BATCH * nh, 64, 0, Bs>>>(
            uu + uOff[b], msb + msOff[b], oo + bOff[b], d, nh, sp);
        hmma_f32<<<dim3(d / 64, 1, 4), 256, HMMA_SMEM, Bs>>>(
            oo + bOff[b], Wo[b], nullptr, 0,
            o2 + bOff[b], d, 0,
            0, d, d, BATCH, BATCH, d / 4, 0, 1.0f);
        // lift: fp16 single-pass, transB, z = slot
        hmma_h16<<<dim3(DLLM / 64, 1, s), 256, H16_SMEM, Bs>>>(
            o2 + bOff[b], Wlift[b], blift[b], DLLM,
            prefix + (size_t)slotBase[b] * DLLM, 16 * DLLM, DLLM,
            (long long)d * DLLM, d, DLLM, BATCH, BATCH, 1);
        ln_kernel<<<BATCH * s, 256, 0, Bs>>>(
            prefix, lng, lnb, (float*)d_out, slotBase[b], s);
        cudaEventRecord(g_si.evD[b], Bs);
    }

    for (int b = 0; b < 3; b++) cudaStreamWaitEvent(0, g_si.evD[b], 0);
}